// round 14
// baseline (speedup 1.0000x reference)
#include <cuda_runtime.h>
#include <cuda_bf16.h>
#include <cstdint>

#define RD 64
#define UD 64
#define VD 64
#define HD 128
#define XD 64
#define NB 8
#define IJ 1024
#define TM 128           // token tile
#define HC 64            // h per CTA (hblk)
#define RRG 32           // rr per CTA

#define ROWB 144
#define VTILEB (128 * ROWB)        // 18432
#define TILEB  (64 * ROWB)         // 9216
#define SOFF_VHI 0
#define SOFF_VLO VTILEB
#define SOFF_BUF (2 * VTILEB)
#define BUFB (4 * TILEB)           // [AHI][ALO][WHI][WLO]
#define SMEM_TOTAL (2 * VTILEB + 2 * BUFB)   // 110592 -> 2 CTAs/SM

// ---------------- gmem scratch ----------------
__device__ float g_rT[NB * RD * IJ];                               // r^T, 2MB
__device__ __align__(16) unsigned short g_ahi[NB * RD * VD * HD];  // A split [n][rr][v][h]
__device__ __align__(16) unsigned short g_alo[NB * RD * VD * HD];
__device__ __align__(16) unsigned short g_vhi[NB * IJ * VD];       // V split [n][m][v]
__device__ __align__(16) unsigned short g_vlo[NB * IJ * VD];
__device__ __align__(16) unsigned short g_w2hi[RD * XD * HD];      // w2 split [rr][x][h]
__device__ __align__(16) unsigned short g_w2lo[RD * XD * HD];

// ---------------- helpers ----------------
__device__ __forceinline__ uint32_t smem_u32(const void* p) {
    uint32_t a;
    asm("{ .reg .u64 t; cvta.to.shared.u64 t, %1; cvt.u32.u64 %0, t; }" : "=r"(a) : "l"(p));
    return a;
}
__device__ __forceinline__ void cp16(uint32_t dst, const void* src) {
    asm volatile("cp.async.cg.shared.global [%0], [%1], 16;" :: "r"(dst), "l"(src));
}
#define CP_COMMIT() asm volatile("cp.async.commit_group;" ::: "memory")
#define CP_WAIT0()  asm volatile("cp.async.wait_group 0;" ::: "memory")

__device__ __forceinline__ void ldsm4(uint32_t& r0, uint32_t& r1, uint32_t& r2, uint32_t& r3,
                                      uint32_t addr) {
    asm volatile("ldmatrix.sync.aligned.m8n8.x4.shared.b16 {%0,%1,%2,%3}, [%4];"
                 : "=r"(r0), "=r"(r1), "=r"(r2), "=r"(r3) : "r"(addr));
}
__device__ __forceinline__ void ldsm4t(uint32_t& r0, uint32_t& r1, uint32_t& r2, uint32_t& r3,
                                       uint32_t addr) {
    asm volatile("ldmatrix.sync.aligned.m8n8.x4.trans.shared.b16 {%0,%1,%2,%3}, [%4];"
                 : "=r"(r0), "=r"(r1), "=r"(r2), "=r"(r3) : "r"(addr));
}
__device__ __forceinline__ void mma_bf16(float* d, const uint32_t a[4],
                                         uint32_t b0, uint32_t b1) {
    asm volatile(
        "mma.sync.aligned.m16n8k16.row.col.f32.bf16.bf16.f32 "
        "{%0,%1,%2,%3}, {%4,%5,%6,%7}, {%8,%9}, {%0,%1,%2,%3};"
        : "+f"(d[0]), "+f"(d[1]), "+f"(d[2]), "+f"(d[3])
        : "r"(a[0]), "r"(a[1]), "r"(a[2]), "r"(a[3]), "r"(b0), "r"(b1));
}
__device__ __forceinline__ void splitf(float x, unsigned short& hi, unsigned short& lo) {
    __nv_bfloat16 h = __float2bfloat16(x);
    __nv_bfloat16 l = __float2bfloat16(x - __bfloat162float(h));
    hi = __bfloat16_as_ushort(h);
    lo = __bfloat16_as_ushort(l);
}
__device__ __forceinline__ void split2(float p0, float p1, uint32_t& hp, uint32_t& lp) {
    asm("cvt.rn.bf16x2.f32 %0, %1, %2;" : "=r"(hp) : "f"(p1), "f"(p0));
    float h0 = __uint_as_float(hp << 16);
    float h1 = __uint_as_float(hp & 0xffff0000u);
    float l0 = p0 - h0, l1 = p1 - h1;
    asm("cvt.rn.bf16x2.f32 %0, %1, %2;" : "=r"(lp) : "f"(l1), "f"(l0));
}

__device__ __forceinline__ void load_afrags(uint32_t f[4][4], uint32_t abase, int m0, int lane) {
    const uint32_t aaddr = abase + (uint32_t)(m0 + (lane & 15)) * ROWB
                         + (uint32_t)((lane >> 4) << 3) * 2;
#pragma unroll
    for (int kk = 0; kk < 4; kk++)
        ldsm4(f[kk][0], f[kk][1], f[kk][2], f[kk][3], aaddr + kk * 32);
}

// ---------------------------------------------------------------------------
// kernPrep: ALL precompute in one launch (1600 CTAs x 256 thr).
//  b in [0,512):    kernA part — A[n,rr,v,h]=sum_u w1*u, split; zero out
//  b in [512,1024): r transpose
//  b in [512+512,1536): V split
//  b in [1536,1600): w2 split
// ---------------------------------------------------------------------------
__global__ __launch_bounds__(256) void kernPrep(const float* __restrict__ r,
                                                const float* __restrict__ u,
                                                const float* __restrict__ v,
                                                const float* __restrict__ w1,
                                                const float* __restrict__ w2,
                                                float* __restrict__ out) {
    const int b = blockIdx.x;
    const int t = threadIdx.x;

    if (b < 512) {
        // ---- A contraction + split, 8 warps = 8 consecutive vv ----
        const int rr = b & 63;
        const int vv0 = (b >> 6) * 8;
        const int vloc = t >> 5;             // 0..7
        const int h4 = (t & 31) * 4;         // 0..124
        const int vv = vv0 + vloc;

        // zero out: 512 CTAs x 256 thr x 4 floats = 524288
        *(float4*)&out[(size_t)(b * 256 + t) * 4] = make_float4(0.f, 0.f, 0.f, 0.f);

        __shared__ float us[8][NB][UD];      // [vloc][n][uu] = u[n,rr,uu,vv0+vloc]
        for (int idx = t; idx < NB * UD; idx += 256) {
            int n = idx >> 6, uu = idx & 63;
            float4 ua = *(const float4*)&u[((n * RD + rr) * UD + uu) * VD + vv0];
            float4 ub = *(const float4*)&u[((n * RD + rr) * UD + uu) * VD + vv0 + 4];
            us[0][n][uu] = ua.x; us[1][n][uu] = ua.y;
            us[2][n][uu] = ua.z; us[3][n][uu] = ua.w;
            us[4][n][uu] = ub.x; us[5][n][uu] = ub.y;
            us[6][n][uu] = ub.z; us[7][n][uu] = ub.w;
        }
        __syncthreads();

        float acc[NB][4];
#pragma unroll
        for (int n = 0; n < NB; n++)
#pragma unroll
            for (int j = 0; j < 4; j++) acc[n][j] = 0.f;

        const float* w1p = w1 + ((size_t)(rr * UD) * VD + vv) * HD + h4;
#pragma unroll 8
        for (int uu = 0; uu < UD; uu++) {
            float4 wv = *(const float4*)(w1p + (size_t)uu * (VD * HD));
#pragma unroll
            for (int n = 0; n < NB; n++) {
                float s = us[vloc][n][uu];
                acc[n][0] = fmaf(wv.x, s, acc[n][0]);
                acc[n][1] = fmaf(wv.y, s, acc[n][1]);
                acc[n][2] = fmaf(wv.z, s, acc[n][2]);
                acc[n][3] = fmaf(wv.w, s, acc[n][3]);
            }
        }
#pragma unroll
        for (int n = 0; n < NB; n++) {
            ushort4 hi4, lo4;
            splitf(acc[n][0], hi4.x, lo4.x);
            splitf(acc[n][1], hi4.y, lo4.y);
            splitf(acc[n][2], hi4.z, lo4.z);
            splitf(acc[n][3], hi4.w, lo4.w);
            const size_t o = ((size_t)(n * RD + rr) * VD + vv) * HD + h4;
            *(ushort4*)&g_ahi[o] = hi4;
            *(ushort4*)&g_alo[o] = lo4;
        }
    } else if (b < 1024) {
        const int bb = b - 512;
        const int n = bb >> 6, rr = bb & 63;
        for (int tt = t; tt < IJ; tt += 256)
            g_rT[(n * RD + rr) * IJ + tt] = r[(n * IJ + tt) * RD + rr];
    } else if (b < 1536) {
        for (int i = (b - 1024) * 256 + t; i < NB * IJ * VD; i += 512 * 256) {
            unsigned short hi, lo;
            splitf(v[i], hi, lo);
            g_vhi[i] = hi;
            g_vlo[i] = lo;
        }
    } else {
        const int rr = b - 1536;
        const int h = t & 127;
        for (int x = t >> 7; x < XD; x += 2) {
            unsigned short hi, lo;
            splitf(w2[(x * RD + rr) * HD + h], hi, lo);
            g_w2hi[(rr * XD + x) * HD + h] = hi;
            g_w2lo[(rr * XD + x) * HD + h] = lo;
        }
    }
}

// ---------------------------------------------------------------------------
// kernB: 256 thr, tile 128m x 64c, single-barrier cp.async pipeline,
// stage-1 processes two h-chunks per pass (4 accumulator chains).
// ---------------------------------------------------------------------------
extern __shared__ unsigned char smemB[];

__device__ __forceinline__ void issue_fills(uint32_t sbuf, int n, int rr, int h0g, int tid) {
    const unsigned short* a1 = g_ahi + ((size_t)(n * RD + rr) * VD) * HD + h0g;
    const unsigned short* a2 = g_alo + ((size_t)(n * RD + rr) * VD) * HD + h0g;
#pragma unroll
    for (int j = 0; j < 2; j++) {
        int i = tid + j * 256;               // 0..511
        int row = i >> 3, c = i & 7;
        uint32_t dst = sbuf + row * ROWB + c * 16;
        cp16(dst,             a1 + (size_t)row * HD + c * 8);
        cp16(dst + TILEB,     a2 + (size_t)row * HD + c * 8);
        const unsigned short* w1p = g_w2hi + (size_t)(rr * XD + row) * HD + h0g + c * 8;
        const unsigned short* w2p = g_w2lo + (size_t)(rr * XD + row) * HD + h0g + c * 8;
        cp16(dst + 2 * TILEB, w1p);
        cp16(dst + 3 * TILEB, w2p);
    }
}

__global__ __launch_bounds__(256, 2) void kernB(float* __restrict__ out) {
    const uint32_t sb = smem_u32(smemB);
    const int tid = threadIdx.x, lane = tid & 31, w = tid >> 5;
    const int tile = blockIdx.x, n = blockIdx.y, z = blockIdx.z;
    const int token0 = tile * TM;
    const int h0g = (z & 1) * HC;
    const int rr0 = (z >> 1) * RRG;
    const int m0 = w * 16;
    const int mrow = lane >> 2;
    const int stag = (blockIdx.x & 1) * (RRG / 2);

    issue_fills(sb + SOFF_BUF, n, rr0 + stag, h0g, tid);
    CP_COMMIT();

    // V tile fill (once)
    {
        const uint4* s1 = (const uint4*)(g_vhi + (size_t)(n * IJ + token0) * VD);
        const uint4* s2 = (const uint4*)(g_vlo + (size_t)(n * IJ + token0) * VD);
#pragma unroll
        for (int j = 0; j < 4; j++) {
            int i = tid + j * 256;
            int row = i >> 3, c = i & 7;
            *(uint4*)(smemB + SOFF_VHI + row * ROWB + c * 16) = s1[i];
            *(uint4*)(smemB + SOFF_VLO + row * ROWB + c * 16) = s2[i];
        }
    }
    __syncthreads();

    uint32_t vhi[4][4], vlo[4][4];
    load_afrags(vhi, sb + SOFF_VHI, m0, lane);
    load_afrags(vlo, sb + SOFF_VLO, m0, lane);

    const uint32_t toff = (uint32_t)(((lane >> 3) & 1) * 8 + (lane & 7)) * ROWB
                        + (uint32_t)((lane >> 4) << 3) * 2;
    const uint32_t woff = (uint32_t)(((lane >> 4) << 3) + (lane & 7)) * ROWB
                        + (uint32_t)(((lane >> 3) & 1) << 3) * 2;

    float oc[8][4];
#pragma unroll
    for (int t2 = 0; t2 < 8; t2++)
#pragma unroll
        for (int j = 0; j < 4; j++) oc[t2][j] = 0.f;

    for (int rl = 0; rl < RRG; rl++) {
        const int rr = rr0 + ((rl + stag) & (RRG - 1));
        const uint32_t sbuf = sb + SOFF_BUF + (rl & 1) * BUFB;

        const float rsc0 = g_rT[(n * RD + rr) * IJ + token0 + m0 + mrow];
        const float rsc8 = g_rT[(n * RD + rr) * IJ + token0 + m0 + mrow + 8];

        CP_WAIT0();
        __syncthreads();
        if (rl + 1 < RRG) {
            issue_fills(sb + SOFF_BUF + ((rl & 1) ^ 1) * BUFB,
                        n, rr0 + ((rl + 1 + stag) & (RRG - 1)), h0g, tid);
            CP_COMMIT();
        }

        // ---- two h-chunks (32 cols) per pass: 4 stage-1 chains ----
#pragma unroll
        for (int cp = 0; cp < 2; cp++) {
            const uint32_t oa = cp * 64;             // byte offset of chunk a
            const uint32_t ob = oa + 32;             // chunk b
            float p0[4] = {0.f,0.f,0.f,0.f}, p1[4] = {0.f,0.f,0.f,0.f};
            float p2[4] = {0.f,0.f,0.f,0.f}, p3[4] = {0.f,0.f,0.f,0.f};
#pragma unroll
            for (int kk = 0; kk < 4; kk++) {
                uint32_t b0, b1, b2, b3;
                ldsm4t(b0, b1, b2, b3, sbuf + toff + kk * 16 * ROWB + oa);
                mma_bf16(p0, vhi[kk], b0, b1);
                mma_bf16(p1, vhi[kk], b2, b3);
                mma_bf16(p0, vlo[kk], b0, b1);
                mma_bf16(p1, vlo[kk], b2, b3);
                ldsm4t(b0, b1, b2, b3, sbuf + toff + kk * 16 * ROWB + ob);
                mma_bf16(p2, vhi[kk], b0, b1);
                mma_bf16(p3, vhi[kk], b2, b3);
                mma_bf16(p2, vlo[kk], b0, b1);
                mma_bf16(p3, vlo[kk], b2, b3);
            }
#pragma unroll
            for (int kk = 0; kk < 4; kk++) {
                uint32_t b0, b1, b2, b3;
                ldsm4t(b0, b1, b2, b3, sbuf + TILEB + toff + kk * 16 * ROWB + oa);
                mma_bf16(p0, vhi[kk], b0, b1);
                mma_bf16(p1, vhi[kk], b2, b3);
                ldsm4t(b0, b1, b2, b3, sbuf + TILEB + toff + kk * 16 * ROWB + ob);
                mma_bf16(p2, vhi[kk], b0, b1);
                mma_bf16(p3, vhi[kk], b2, b3);
            }

            // epilogue for both chunks: 8 independent split2s
            uint32_t fahi[4], falo[4], fbhi[4], fblo[4];
            split2(fmaxf(p0[0], 0.f) * rsc0, fmaxf(p0[1], 0.f) * rsc0, fahi[0], falo[0]);
            split2(fmaxf(p0[2], 0.f) * rsc8, fmaxf(p0[3], 0.f) * rsc8, fahi[1], falo[1]);
            split2(fmaxf(p1[0], 0.f) * rsc0, fmaxf(p1[1], 0.f) * rsc0, fahi[2], falo[2]);
            split2(fmaxf(p1[2], 0.f) * rsc8, fmaxf(p1[3], 0.f) * rsc8, fahi[3], falo[3]);
            split2(fmaxf(p2[0], 0.f) * rsc0, fmaxf(p2[1], 0.f) * rsc0, fbhi[0], fblo[0]);
            split2(fmaxf(p2[2], 0.f) * rsc8, fmaxf(p2[3], 0.f) * rsc8, fbhi[1], fblo[1]);
            split2(fmaxf(p3[0], 0.f) * rsc0, fmaxf(p3[1], 0.f) * rsc0, fbhi[2], fblo[2]);
            split2(fmaxf(p3[2], 0.f) * rsc8, fmaxf(p3[3], 0.f) * rsc8, fbhi[3], fblo[3]);

            // stage-2 for K-chunks a and b
#pragma unroll
            for (int nt = 0; nt < 4; nt++) {
                uint32_t b0, b1, b2, b3;
                ldsm4(b0, b1, b2, b3, sbuf + 2 * TILEB + woff + nt * 16 * ROWB + oa);
                mma_bf16(oc[2 * nt],     fahi, b0, b1);
                mma_bf16(oc[2 * nt + 1], fahi, b2, b3);
                mma_bf16(oc[2 * nt],     falo, b0, b1);
                mma_bf16(oc[2 * nt + 1], falo, b2, b3);
                ldsm4(b0, b1, b2, b3, sbuf + 2 * TILEB + woff + nt * 16 * ROWB + ob);
                mma_bf16(oc[2 * nt],     fbhi, b0, b1);
                mma_bf16(oc[2 * nt + 1], fbhi, b2, b3);
                mma_bf16(oc[2 * nt],     fblo, b0, b1);
                mma_bf16(oc[2 * nt + 1], fblo, b2, b3);
                ldsm4(b0, b1, b2, b3, sbuf + 3 * TILEB + woff + nt * 16 * ROWB + oa);
                mma_bf16(oc[2 * nt],     fahi, b0, b1);
                mma_bf16(oc[2 * nt + 1], fahi, b2, b3);
                ldsm4(b0, b1, b2, b3, sbuf + 3 * TILEB + woff + nt * 16 * ROWB + ob);
                mma_bf16(oc[2 * nt],     fbhi, b0, b1);
                mma_bf16(oc[2 * nt + 1], fbhi, b2, b3);
            }
        }
    }

    // final epilogue: 4 partial CTAs per out element
    {
        float* op = out + (size_t)(n * IJ + token0 + m0 + mrow) * XD;
#pragma unroll
        for (int nt = 0; nt < 8; nt++) {
            const int x = nt * 8 + 2 * (lane & 3);
            atomicAdd(op + x,     oc[nt][0]);
            atomicAdd(op + x + 1, oc[nt][1]);
            atomicAdd(op + 8 * XD + x,     oc[nt][2]);
            atomicAdd(op + 8 * XD + x + 1, oc[nt][3]);
        }
    }
}

// ---------------------------------------------------------------------------
extern "C" void kernel_launch(void* const* d_in, const int* in_sizes, int n_in,
                              void* d_out, int out_size) {
    const float* r  = (const float*)d_in[0];
    const float* u  = (const float*)d_in[1];
    const float* v  = (const float*)d_in[2];
    const float* w1 = (const float*)d_in[3];
    const float* w2 = (const float*)d_in[4];
    float* out = (float*)d_out;
    (void)in_sizes; (void)n_in; (void)out_size;

    static int attr_done = 0;
    if (!attr_done) {
        cudaFuncSetAttribute(kernB, cudaFuncAttributeMaxDynamicSharedMemorySize, SMEM_TOTAL);
        attr_done = 1;
    }

    kernPrep<<<1600, 256>>>(r, u, v, w1, w2, out);
    kernB<<<dim3(IJ / TM, NB, 4), 256, SMEM_TOTAL>>>(out);
}

// round 15
// speedup vs baseline: 1.3586x; 1.3586x over previous
#include <cuda_runtime.h>
#include <cuda_fp16.h>
#include <cstdint>

#define RD 64
#define UD 64
#define VD 64
#define HD 128
#define XD 64
#define NB 8
#define IJ 1024
#define TM 128           // token tile
#define HC 64            // h per CTA (hblk)
#define RRG 32           // rr per CTA

#define ROWB 144
#define VTILEB (128 * ROWB)        // 18432
#define TILEB  (64 * ROWB)         // 9216
#define SOFF_VHI 0
#define SOFF_VLO VTILEB
#define SOFF_BUF (2 * VTILEB)
#define BUFB (2 * TILEB)           // [A16][W16]
#define SMEM_TOTAL (2 * VTILEB + 2 * BUFB)   // 73728

// ---------------- gmem scratch ----------------
__device__ float g_rT[NB * RD * IJ];                               // r^T, 2MB
__device__ __align__(16) unsigned short g_a16[NB * RD * VD * HD];  // A fp16 [n][rr][v][h]
__device__ __align__(16) unsigned short g_vhi[NB * IJ * VD];       // V fp16 split [n][m][v]
__device__ __align__(16) unsigned short g_vlo[NB * IJ * VD];
__device__ __align__(16) unsigned short g_w216[RD * XD * HD];      // w2 fp16 [rr][x][h]

// ---------------- helpers ----------------
__device__ __forceinline__ uint32_t smem_u32(const void* p) {
    uint32_t a;
    asm("{ .reg .u64 t; cvta.to.shared.u64 t, %1; cvt.u32.u64 %0, t; }" : "=r"(a) : "l"(p));
    return a;
}
__device__ __forceinline__ void cp16(uint32_t dst, const void* src) {
    asm volatile("cp.async.cg.shared.global [%0], [%1], 16;" :: "r"(dst), "l"(src));
}
#define CP_COMMIT() asm volatile("cp.async.commit_group;" ::: "memory")
#define CP_WAIT0()  asm volatile("cp.async.wait_group 0;" ::: "memory")

__device__ __forceinline__ void ldsm4(uint32_t& r0, uint32_t& r1, uint32_t& r2, uint32_t& r3,
                                      uint32_t addr) {
    asm volatile("ldmatrix.sync.aligned.m8n8.x4.shared.b16 {%0,%1,%2,%3}, [%4];"
                 : "=r"(r0), "=r"(r1), "=r"(r2), "=r"(r3) : "r"(addr));
}
__device__ __forceinline__ void ldsm4t(uint32_t& r0, uint32_t& r1, uint32_t& r2, uint32_t& r3,
                                       uint32_t addr) {
    asm volatile("ldmatrix.sync.aligned.m8n8.x4.trans.shared.b16 {%0,%1,%2,%3}, [%4];"
                 : "=r"(r0), "=r"(r1), "=r"(r2), "=r"(r3) : "r"(addr));
}
__device__ __forceinline__ void mma_f16(float* d, const uint32_t a[4],
                                        uint32_t b0, uint32_t b1) {
    asm volatile(
        "mma.sync.aligned.m16n8k16.row.col.f32.f16.f16.f32 "
        "{%0,%1,%2,%3}, {%4,%5,%6,%7}, {%8,%9}, {%0,%1,%2,%3};"
        : "+f"(d[0]), "+f"(d[1]), "+f"(d[2]), "+f"(d[3])
        : "r"(a[0]), "r"(a[1]), "r"(a[2]), "r"(a[3]), "r"(b0), "r"(b1));
}
// fp16 2-term split of a scalar
__device__ __forceinline__ void splitfh(float x, unsigned short& hi, unsigned short& lo) {
    __half h = __float2half_rn(x);
    __half l = __float2half_rn(x - __half2float(h));
    hi = __half_as_ushort(h);
    lo = __half_as_ushort(l);
}
// packed fp16 split: hp = {f16(p1), f16(p0)} (p0 low), lp = residuals
__device__ __forceinline__ void split2h(float p0, float p1, uint32_t& hp, uint32_t& lp) {
    asm("cvt.rn.f16x2.f32 %0, %1, %2;" : "=r"(hp) : "f"(p1), "f"(p0));
    float h0, h1;
    asm("{ .reg .f16 a,b; mov.b32 {a,b}, %2; cvt.f32.f16 %0, a; cvt.f32.f16 %1, b; }"
        : "=f"(h0), "=f"(h1) : "r"(hp));
    float l0 = p0 - h0, l1 = p1 - h1;
    asm("cvt.rn.f16x2.f32 %0, %1, %2;" : "=r"(lp) : "f"(l1), "f"(l0));
}

__device__ __forceinline__ void load_afrags(uint32_t f[4][4], uint32_t abase, int m0, int lane) {
    const uint32_t aaddr = abase + (uint32_t)(m0 + (lane & 15)) * ROWB
                         + (uint32_t)((lane >> 4) << 3) * 2;
#pragma unroll
    for (int kk = 0; kk < 4; kk++)
        ldsm4(f[kk][0], f[kk][1], f[kk][2], f[kk][3], aaddr + kk * 32);
}

// ---------------------------------------------------------------------------
// kernPre: merged r-transpose / V-split(fp16) / w2(fp16)
// ---------------------------------------------------------------------------
__global__ __launch_bounds__(256) void kernPre(const float* __restrict__ r,
                                               const float* __restrict__ v,
                                               const float* __restrict__ w2) {
    const int b = blockIdx.x;
    if (b < 512) {
        const int n = b >> 6, rr = b & 63;
        for (int t = threadIdx.x; t < IJ; t += 256)
            g_rT[(n * RD + rr) * IJ + t] = r[(n * IJ + t) * RD + rr];
    } else if (b < 1024) {
        for (int i = (b - 512) * 256 + threadIdx.x; i < NB * IJ * VD; i += 512 * 256) {
            unsigned short hi, lo;
            splitfh(v[i], hi, lo);
            g_vhi[i] = hi;
            g_vlo[i] = lo;
        }
    } else {
        const int rr = b - 1024;
        const int h = threadIdx.x & 127;
        for (int x = threadIdx.x >> 7; x < XD; x += 2)
            g_w216[(rr * XD + x) * HD + h] =
                __half_as_ushort(__float2half_rn(w2[(x * RD + rr) * HD + h]));
    }
}

// ---------------------------------------------------------------------------
// kernA: A[n,rr,v,h] = sum_u w1*u -> fp16 g_a16[n][rr][v][h]; zeroes out.
// grid (64 rr, 16 v-groups), 128 thr: warp <-> one vv, thread <-> 4 h (float4).
// ---------------------------------------------------------------------------
__global__ __launch_bounds__(128) void kernA(const float* __restrict__ u,
                                             const float* __restrict__ w1,
                                             float* __restrict__ out) {
    const int rr = blockIdx.x;
    const int vv0 = blockIdx.y * 4;
    const int t = threadIdx.x;
    const int vloc = t >> 5;
    const int h4 = (t & 31) * 4;
    const int vv = vv0 + vloc;

    *(float4*)&out[(size_t)((blockIdx.y * RD + blockIdx.x) * 128 + t) * 4] =
        make_float4(0.f, 0.f, 0.f, 0.f);

    __shared__ float us[4][NB][UD];
    for (int idx = t; idx < NB * UD; idx += 128) {
        int n = idx >> 6, uu = idx & 63;
        float4 uv = *(const float4*)&u[((n * RD + rr) * UD + uu) * VD + vv0];
        us[0][n][uu] = uv.x;
        us[1][n][uu] = uv.y;
        us[2][n][uu] = uv.z;
        us[3][n][uu] = uv.w;
    }
    __syncthreads();

    float acc[NB][4];
#pragma unroll
    for (int n = 0; n < NB; n++)
#pragma unroll
        for (int j = 0; j < 4; j++) acc[n][j] = 0.f;

    const float* w1p = w1 + ((size_t)(rr * UD) * VD + vv) * HD + h4;
#pragma unroll 8
    for (int uu = 0; uu < UD; uu++) {
        float4 wv = *(const float4*)(w1p + (size_t)uu * (VD * HD));
#pragma unroll
        for (int n = 0; n < NB; n++) {
            float s = us[vloc][n][uu];
            acc[n][0] = fmaf(wv.x, s, acc[n][0]);
            acc[n][1] = fmaf(wv.y, s, acc[n][1]);
            acc[n][2] = fmaf(wv.z, s, acc[n][2]);
            acc[n][3] = fmaf(wv.w, s, acc[n][3]);
        }
    }
#pragma unroll
    for (int n = 0; n < NB; n++) {
        ushort4 h4v;
        h4v.x = __half_as_ushort(__float2half_rn(acc[n][0]));
        h4v.y = __half_as_ushort(__float2half_rn(acc[n][1]));
        h4v.z = __half_as_ushort(__float2half_rn(acc[n][2]));
        h4v.w = __half_as_ushort(__float2half_rn(acc[n][3]));
        *(ushort4*)&g_a16[((size_t)(n * RD + rr) * VD + vv) * HD + h4] = h4v;
    }
}

// ---------------------------------------------------------------------------
// kernB: 256 thr, tile 128m x 64c, fp16 asymmetric split:
//   stage1: P = (Vhi + Vlo) * A16   (2 products)
//   stage2: OUT += (Phi + Plo) * W16 (2 products)
// ---------------------------------------------------------------------------
extern __shared__ unsigned char smemB[];

__device__ __forceinline__ void issue_fills(uint32_t sbuf, int n, int rr, int h0g, int tid) {
    const unsigned short* a1 = g_a16 + ((size_t)(n * RD + rr) * VD) * HD + h0g;
#pragma unroll
    for (int j = 0; j < 2; j++) {
        int i = tid + j * 256;               // 0..511
        int row = i >> 3, c = i & 7;
        uint32_t dst = sbuf + row * ROWB + c * 16;
        cp16(dst,         a1 + (size_t)row * HD + c * 8);
        cp16(dst + TILEB, g_w216 + (size_t)(rr * XD + row) * HD + h0g + c * 8);
    }
}

__global__ __launch_bounds__(256, 2) void kernB(float* __restrict__ out) {
    const uint32_t sb = smem_u32(smemB);
    const int tid = threadIdx.x, lane = tid & 31, w = tid >> 5;
    const int tile = blockIdx.x, n = blockIdx.y, z = blockIdx.z;
    const int token0 = tile * TM;
    const int h0g = (z & 1) * HC;
    const int rr0 = (z >> 1) * RRG;
    const int m0 = w * 16;
    const int mrow = lane >> 2;
    const int stag = (blockIdx.x & 1) * (RRG / 2);

    issue_fills(sb + SOFF_BUF, n, rr0 + stag, h0g, tid);
    CP_COMMIT();

    // V tile fill (once): 128 rows x 128B, 144B stride
    {
        const uint4* s1 = (const uint4*)(g_vhi + (size_t)(n * IJ + token0) * VD);
        const uint4* s2 = (const uint4*)(g_vlo + (size_t)(n * IJ + token0) * VD);
#pragma unroll
        for (int j = 0; j < 4; j++) {
            int i = tid + j * 256;
            int row = i >> 3, c = i & 7;
            *(uint4*)(smemB + SOFF_VHI + row * ROWB + c * 16) = s1[i];
            *(uint4*)(smemB + SOFF_VLO + row * ROWB + c * 16) = s2[i];
        }
    }
    __syncthreads();

    uint32_t vhi[4][4], vlo[4][4];
    load_afrags(vhi, sb + SOFF_VHI, m0, lane);
    load_afrags(vlo, sb + SOFF_VLO, m0, lane);

    const uint32_t toff = (uint32_t)(((lane >> 3) & 1) * 8 + (lane & 7)) * ROWB
                        + (uint32_t)((lane >> 4) << 3) * 2;
    const uint32_t woff = (uint32_t)(((lane >> 4) << 3) + (lane & 7)) * ROWB
                        + (uint32_t)(((lane >> 3) & 1) << 3) * 2;

    float oc[8][4];
#pragma unroll
    for (int t2 = 0; t2 < 8; t2++)
#pragma unroll
        for (int j = 0; j < 4; j++) oc[t2][j] = 0.f;

    for (int rl = 0; rl < RRG; rl++) {
        const int rr = rr0 + ((rl + stag) & (RRG - 1));
        const uint32_t sbuf = sb + SOFF_BUF + (rl & 1) * BUFB;

        const float rsc0 = g_rT[(n * RD + rr) * IJ + token0 + m0 + mrow];
        const float rsc8 = g_rT[(n * RD + rr) * IJ + token0 + m0 + mrow + 8];

        CP_WAIT0();
        __syncthreads();
        if (rl + 1 < RRG) {
            issue_fills(sb + SOFF_BUF + ((rl & 1) ^ 1) * BUFB,
                        n, rr0 + ((rl + 1 + stag) & (RRG - 1)), h0g, tid);
            CP_COMMIT();
        }

        // ---- pipelined per h-chunk (16 cols): stage1 -> split -> stage2 ----
#pragma unroll
        for (int c2 = 0; c2 < 4; c2++) {
            float p0[4] = {0.f, 0.f, 0.f, 0.f};
            float p1[4] = {0.f, 0.f, 0.f, 0.f};
#pragma unroll
            for (int kk = 0; kk < 4; kk++) {
                uint32_t b0, b1, b2, b3;
                ldsm4t(b0, b1, b2, b3, sbuf + toff + kk * 16 * ROWB + c2 * 32);
                mma_f16(p0, vhi[kk], b0, b1);
                mma_f16(p1, vhi[kk], b2, b3);
                mma_f16(p0, vlo[kk], b0, b1);
                mma_f16(p1, vlo[kk], b2, b3);
            }

            uint32_t fhi[4], flo[4];
            split2h(fmaxf(p0[0], 0.f) * rsc0, fmaxf(p0[1], 0.f) * rsc0, fhi[0], flo[0]);
            split2h(fmaxf(p0[2], 0.f) * rsc8, fmaxf(p0[3], 0.f) * rsc8, fhi[1], flo[1]);
            split2h(fmaxf(p1[0], 0.f) * rsc0, fmaxf(p1[1], 0.f) * rsc0, fhi[2], flo[2]);
            split2h(fmaxf(p1[2], 0.f) * rsc8, fmaxf(p1[3], 0.f) * rsc8, fhi[3], flo[3]);

#pragma unroll
            for (int nt = 0; nt < 4; nt++) {
                uint32_t b0, b1, b2, b3;
                ldsm4(b0, b1, b2, b3, sbuf + TILEB + woff + nt * 16 * ROWB + c2 * 32);
                mma_f16(oc[2 * nt],     fhi, b0, b1);
                mma_f16(oc[2 * nt + 1], fhi, b2, b3);
                mma_f16(oc[2 * nt],     flo, b0, b1);
                mma_f16(oc[2 * nt + 1], flo, b2, b3);
            }
        }
    }

    // final epilogue: 4 partial CTAs per out element
    {
        float* op = out + (size_t)(n * IJ + token0 + m0 + mrow) * XD;
#pragma unroll
        for (int nt = 0; nt < 8; nt++) {
            const int x = nt * 8 + 2 * (lane & 3);
            atomicAdd(op + x,     oc[nt][0]);
            atomicAdd(op + x + 1, oc[nt][1]);
            atomicAdd(op + 8 * XD + x,     oc[nt][2]);
            atomicAdd(op + 8 * XD + x + 1, oc[nt][3]);
        }
    }
}

// ---------------------------------------------------------------------------
extern "C" void kernel_launch(void* const* d_in, const int* in_sizes, int n_in,
                              void* d_out, int out_size) {
    const float* r  = (const float*)d_in[0];
    const float* u  = (const float*)d_in[1];
    const float* v  = (const float*)d_in[2];
    const float* w1 = (const float*)d_in[3];
    const float* w2 = (const float*)d_in[4];
    float* out = (float*)d_out;
    (void)in_sizes; (void)n_in; (void)out_size;

    static int attr_done = 0;
    if (!attr_done) {
        cudaFuncSetAttribute(kernB, cudaFuncAttributeMaxDynamicSharedMemorySize, SMEM_TOTAL);
        attr_done = 1;
    }

    kernPre<<<1088, 256>>>(r, v, w2);
    kernA<<<dim3(RD, 16), 128>>>(u, w1, out);
    kernB<<<dim3(IJ / TM, NB, 4), 256, SMEM_TOTAL>>>(out);
}

// round 16
// speedup vs baseline: 1.7860x; 1.3146x over previous
#include <cuda_runtime.h>
#include <cuda_fp16.h>
#include <cstdint>

#define RD 64
#define UD 64
#define VD 64
#define HD 128
#define XD 64
#define NB 8
#define IJ 1024
#define TM 128           // token tile
#define HC 64            // h per CTA (hblk)
#define RRG 32           // rr per CTA

#define ROWB 144
#define VTILEB (128 * ROWB)        // 18432
#define TILEB  (64 * ROWB)         // 9216
#define SOFF_V 0
#define SOFF_BUF VTILEB
#define BUFB (2 * TILEB)           // [A16][W16]
#define SMEM_TOTAL (VTILEB + 2 * BUFB)   // 55296 -> 3+ CTAs/SM

// ---------------- gmem scratch ----------------
__device__ float g_rT[NB * RD * IJ];                               // r^T, 2MB
__device__ __align__(16) unsigned short g_a16[NB * RD * VD * HD];  // A fp16 [n][rr][v][h]
__device__ __align__(16) unsigned short g_v16[NB * IJ * VD];       // V fp16 [n][m][v]
__device__ __align__(16) unsigned short g_w216[RD * XD * HD];      // w2 fp16 [rr][x][h]

// ---------------- helpers ----------------
__device__ __forceinline__ uint32_t smem_u32(const void* p) {
    uint32_t a;
    asm("{ .reg .u64 t; cvta.to.shared.u64 t, %1; cvt.u32.u64 %0, t; }" : "=r"(a) : "l"(p));
    return a;
}
__device__ __forceinline__ void cp16(uint32_t dst, const void* src) {
    asm volatile("cp.async.cg.shared.global [%0], [%1], 16;" :: "r"(dst), "l"(src));
}
#define CP_COMMIT() asm volatile("cp.async.commit_group;" ::: "memory")
#define CP_WAIT0()  asm volatile("cp.async.wait_group 0;" ::: "memory")

__device__ __forceinline__ void ldsm4(uint32_t& r0, uint32_t& r1, uint32_t& r2, uint32_t& r3,
                                      uint32_t addr) {
    asm volatile("ldmatrix.sync.aligned.m8n8.x4.shared.b16 {%0,%1,%2,%3}, [%4];"
                 : "=r"(r0), "=r"(r1), "=r"(r2), "=r"(r3) : "r"(addr));
}
__device__ __forceinline__ void ldsm4t(uint32_t& r0, uint32_t& r1, uint32_t& r2, uint32_t& r3,
                                       uint32_t addr) {
    asm volatile("ldmatrix.sync.aligned.m8n8.x4.trans.shared.b16 {%0,%1,%2,%3}, [%4];"
                 : "=r"(r0), "=r"(r1), "=r"(r2), "=r"(r3) : "r"(addr));
}
__device__ __forceinline__ void mma_f16(float* d, const uint32_t a[4],
                                        uint32_t b0, uint32_t b1) {
    asm volatile(
        "mma.sync.aligned.m16n8k16.row.col.f32.f16.f16.f32 "
        "{%0,%1,%2,%3}, {%4,%5,%6,%7}, {%8,%9}, {%0,%1,%2,%3};"
        : "+f"(d[0]), "+f"(d[1]), "+f"(d[2]), "+f"(d[3])
        : "r"(a[0]), "r"(a[1]), "r"(a[2]), "r"(a[3]), "r"(b0), "r"(b1));
}
// pack two floats to f16x2 (p0 in low half)
__device__ __forceinline__ uint32_t pack2h(float p0, float p1) {
    uint32_t r;
    asm("cvt.rn.f16x2.f32 %0, %1, %2;" : "=r"(r) : "f"(p1), "f"(p0));
    return r;
}

__device__ __forceinline__ void load_afrags(uint32_t f[4][4], uint32_t abase, int m0, int lane) {
    const uint32_t aaddr = abase + (uint32_t)(m0 + (lane & 15)) * ROWB
                         + (uint32_t)((lane >> 4) << 3) * 2;
#pragma unroll
    for (int kk = 0; kk < 4; kk++)
        ldsm4(f[kk][0], f[kk][1], f[kk][2], f[kk][3], aaddr + kk * 32);
}

// ---------------------------------------------------------------------------
// kernPre: merged r-transpose / V fp16 / w2 fp16
// ---------------------------------------------------------------------------
__global__ __launch_bounds__(256) void kernPre(const float* __restrict__ r,
                                               const float* __restrict__ v,
                                               const float* __restrict__ w2) {
    const int b = blockIdx.x;
    if (b < 512) {
        const int n = b >> 6, rr = b & 63;
        for (int t = threadIdx.x; t < IJ; t += 256)
            g_rT[(n * RD + rr) * IJ + t] = r[(n * IJ + t) * RD + rr];
    } else if (b < 768) {
        for (int i = (b - 512) * 256 + threadIdx.x; i < NB * IJ * VD; i += 256 * 256)
            g_v16[i] = __half_as_ushort(__float2half_rn(v[i]));
    } else {
        const int rr = b - 768;
        const int h = threadIdx.x & 127;
        for (int x = threadIdx.x >> 7; x < XD; x += 2)
            g_w216[(rr * XD + x) * HD + h] =
                __half_as_ushort(__float2half_rn(w2[(x * RD + rr) * HD + h]));
    }
}

// ---------------------------------------------------------------------------
// kernA: A[n,rr,v,h] = sum_u w1*u -> fp16 g_a16[n][rr][v][h]; zeroes out.
// ---------------------------------------------------------------------------
__global__ __launch_bounds__(128) void kernA(const float* __restrict__ u,
                                             const float* __restrict__ w1,
                                             float* __restrict__ out) {
    const int rr = blockIdx.x;
    const int vv0 = blockIdx.y * 4;
    const int t = threadIdx.x;
    const int vloc = t >> 5;
    const int h4 = (t & 31) * 4;
    const int vv = vv0 + vloc;

    *(float4*)&out[(size_t)((blockIdx.y * RD + blockIdx.x) * 128 + t) * 4] =
        make_float4(0.f, 0.f, 0.f, 0.f);

    __shared__ float us[4][NB][UD];
    for (int idx = t; idx < NB * UD; idx += 128) {
        int n = idx >> 6, uu = idx & 63;
        float4 uv = *(const float4*)&u[((n * RD + rr) * UD + uu) * VD + vv0];
        us[0][n][uu] = uv.x;
        us[1][n][uu] = uv.y;
        us[2][n][uu] = uv.z;
        us[3][n][uu] = uv.w;
    }
    __syncthreads();

    float acc[NB][4];
#pragma unroll
    for (int n = 0; n < NB; n++)
#pragma unroll
        for (int j = 0; j < 4; j++) acc[n][j] = 0.f;

    const float* w1p = w1 + ((size_t)(rr * UD) * VD + vv) * HD + h4;
#pragma unroll 8
    for (int uu = 0; uu < UD; uu++) {
        float4 wv = *(const float4*)(w1p + (size_t)uu * (VD * HD));
#pragma unroll
        for (int n = 0; n < NB; n++) {
            float s = us[vloc][n][uu];
            acc[n][0] = fmaf(wv.x, s, acc[n][0]);
            acc[n][1] = fmaf(wv.y, s, acc[n][1]);
            acc[n][2] = fmaf(wv.z, s, acc[n][2]);
            acc[n][3] = fmaf(wv.w, s, acc[n][3]);
        }
    }
#pragma unroll
    for (int n = 0; n < NB; n++) {
        ushort4 h4v;
        h4v.x = __half_as_ushort(__float2half_rn(acc[n][0]));
        h4v.y = __half_as_ushort(__float2half_rn(acc[n][1]));
        h4v.z = __half_as_ushort(__float2half_rn(acc[n][2]));
        h4v.w = __half_as_ushort(__float2half_rn(acc[n][3]));
        *(ushort4*)&g_a16[((size_t)(n * RD + rr) * VD + vv) * HD + h4] = h4v;
    }
}

// ---------------------------------------------------------------------------
// kernB: 256 thr, tile 128m x 64c, pure fp16 mma with fp32 accumulate.
//   stage1: P = V16 * A16      stage2: OUT += P16 * W16
// 3 CTAs/SM (55.3KB smem), single-barrier cp.async pipeline.
// ---------------------------------------------------------------------------
extern __shared__ unsigned char smemB[];

__device__ __forceinline__ void issue_fills(uint32_t sbuf, int n, int rr, int h0g, int tid) {
    const unsigned short* a1 = g_a16 + ((size_t)(n * RD + rr) * VD) * HD + h0g;
#pragma unroll
    for (int j = 0; j < 2; j++) {
        int i = tid + j * 256;               // 0..511
        int row = i >> 3, c = i & 7;
        uint32_t dst = sbuf + row * ROWB + c * 16;
        cp16(dst,         a1 + (size_t)row * HD + c * 8);
        cp16(dst + TILEB, g_w216 + (size_t)(rr * XD + row) * HD + h0g + c * 8);
    }
}

__global__ __launch_bounds__(256, 3) void kernB(float* __restrict__ out) {
    const uint32_t sb = smem_u32(smemB);
    const int tid = threadIdx.x, lane = tid & 31, w = tid >> 5;
    const int tile = blockIdx.x, n = blockIdx.y, z = blockIdx.z;
    const int token0 = tile * TM;
    const int h0g = (z & 1) * HC;
    const int rr0 = (z >> 1) * RRG;
    const int m0 = w * 16;
    const int mrow = lane >> 2;
    const int stag = (blockIdx.x & 3) * 8;   // phase stagger through the rr ring

    issue_fills(sb + SOFF_BUF, n, rr0 + (stag & (RRG - 1)), h0g, tid);
    CP_COMMIT();

    // V tile fill (once): 128 rows x 128B, 144B stride
    {
        const uint4* s1 = (const uint4*)(g_v16 + (size_t)(n * IJ + token0) * VD);
#pragma unroll
        for (int j = 0; j < 4; j++) {
            int i = tid + j * 256;
            int row = i >> 3, c = i & 7;
            *(uint4*)(smemB + SOFF_V + row * ROWB + c * 16) = s1[i];
        }
    }
    __syncthreads();

    uint32_t vf[4][4];
    load_afrags(vf, sb + SOFF_V, m0, lane);

    const uint32_t toff = (uint32_t)(((lane >> 3) & 1) * 8 + (lane & 7)) * ROWB
                        + (uint32_t)((lane >> 4) << 3) * 2;
    const uint32_t woff = (uint32_t)(((lane >> 4) << 3) + (lane & 7)) * ROWB
                        + (uint32_t)(((lane >> 3) & 1) << 3) * 2;

    float oc[8][4];
#pragma unroll
    for (int t2 = 0; t2 < 8; t2++)
#pragma unroll
        for (int j = 0; j < 4; j++) oc[t2][j] = 0.f;

    for (int rl = 0; rl < RRG; rl++) {
        const int rr = rr0 + ((rl + stag) & (RRG - 1));
        const uint32_t sbuf = sb + SOFF_BUF + (rl & 1) * BUFB;

        const float rsc0 = g_rT[(n * RD + rr) * IJ + token0 + m0 + mrow];
        const float rsc8 = g_rT[(n * RD + rr) * IJ + token0 + m0 + mrow + 8];

        CP_WAIT0();
        __syncthreads();
        if (rl + 1 < RRG) {
            issue_fills(sb + SOFF_BUF + ((rl & 1) ^ 1) * BUFB,
                        n, rr0 + ((rl + 1 + stag) & (RRG - 1)), h0g, tid);
            CP_COMMIT();
        }

        // ---- pipelined per h-chunk (16 cols): stage1 -> cvt -> stage2 ----
#pragma unroll
        for (int c2 = 0; c2 < 4; c2++) {
            float p0[4] = {0.f, 0.f, 0.f, 0.f};
            float p1[4] = {0.f, 0.f, 0.f, 0.f};
#pragma unroll
            for (int kk = 0; kk < 4; kk++) {
                uint32_t b0, b1, b2, b3;
                ldsm4t(b0, b1, b2, b3, sbuf + toff + kk * 16 * ROWB + c2 * 32);
                mma_f16(p0, vf[kk], b0, b1);
                mma_f16(p1, vf[kk], b2, b3);
            }

            uint32_t fp[4];
            fp[0] = pack2h(fmaxf(p0[0], 0.f) * rsc0, fmaxf(p0[1], 0.f) * rsc0);
            fp[1] = pack2h(fmaxf(p0[2], 0.f) * rsc8, fmaxf(p0[3], 0.f) * rsc8);
            fp[2] = pack2h(fmaxf(p1[0], 0.f) * rsc0, fmaxf(p1[1], 0.f) * rsc0);
            fp[3] = pack2h(fmaxf(p1[2], 0.f) * rsc8, fmaxf(p1[3], 0.f) * rsc8);

#pragma unroll
            for (int nt = 0; nt < 4; nt++) {
                uint32_t b0, b1, b2, b3;
                ldsm4(b0, b1, b2, b3, sbuf + TILEB + woff + nt * 16 * ROWB + c2 * 32);
                mma_f16(oc[2 * nt],     fp, b0, b1);
                mma_f16(oc[2 * nt + 1], fp, b2, b3);
            }
        }
    }

    // final epilogue: 4 partial CTAs per out element
    {
        float* op = out + (size_t)(n * IJ + token0 + m0 + mrow) * XD;
#pragma unroll
        for (int nt = 0; nt < 8; nt++) {
            const int x = nt * 8 + 2 * (lane & 3);
            atomicAdd(op + x,     oc[nt][0]);
            atomicAdd(op + x + 1, oc[nt][1]);
            atomicAdd(op + 8 * XD + x,     oc[nt][2]);
            atomicAdd(op + 8 * XD + x + 1, oc[nt][3]);
        }
    }
}

// ---------------------------------------------------------------------------
extern "C" void kernel_launch(void* const* d_in, const int* in_sizes, int n_in,
                              void* d_out, int out_size) {
    const float* r  = (const float*)d_in[0];
    const float* u  = (const float*)d_in[1];
    const float* v  = (const float*)d_in[2];
    const float* w1 = (const float*)d_in[3];
    const float* w2 = (const float*)d_in[4];
    float* out = (float*)d_out;
    (void)in_sizes; (void)n_in; (void)out_size;

    static int attr_done = 0;
    if (!attr_done) {
        cudaFuncSetAttribute(kernB, cudaFuncAttributeMaxDynamicSharedMemorySize, SMEM_TOTAL);
        attr_done = 1;
    }

    kernPre<<<832, 256>>>(r, v, w2);
    kernA<<<dim3(RD, 16), 128>>>(u, w1, out);
    kernB<<<dim3(IJ / TM, NB, 4), 256, SMEM_TOTAL>>>(out);
}

// round 17
// speedup vs baseline: 1.8887x; 1.0575x over previous
#include <cuda_runtime.h>
#include <cuda_fp16.h>
#include <cstdint>

#define RD 64
#define UD 64
#define VD 64
#define HD 128
#define XD 64
#define NB 8
#define IJ 1024
#define TM 64            // token tile (quarter-size CTAs)
#define HC 64            // h per CTA (hblk)
#define RRG 16           // rr per CTA (4 rr-groups)

#define ROWB 144
#define VTILEB (64 * ROWB)         // 9216
#define TILEB  (64 * ROWB)         // 9216
#define SOFF_V 0
#define SOFF_BUF VTILEB
#define BUFB (2 * TILEB)           // [A16][W16]
#define SMEM_TOTAL (VTILEB + 2 * BUFB)   // 46080 -> 4 CTAs/SM

// ---------------- gmem scratch ----------------
__device__ float g_rT[NB * RD * IJ];                               // r^T, 2MB
__device__ __align__(16) unsigned short g_a16[NB * RD * VD * HD];  // A fp16 [n][rr][v][h]
__device__ __align__(16) unsigned short g_v16[NB * IJ * VD];       // V fp16 [n][m][v]
__device__ __align__(16) unsigned short g_w216[RD * XD * HD];      // w2 fp16 [rr][x][h]

// ---------------- helpers ----------------
__device__ __forceinline__ uint32_t smem_u32(const void* p) {
    uint32_t a;
    asm("{ .reg .u64 t; cvta.to.shared.u64 t, %1; cvt.u32.u64 %0, t; }" : "=r"(a) : "l"(p));
    return a;
}
__device__ __forceinline__ void cp16(uint32_t dst, const void* src) {
    asm volatile("cp.async.cg.shared.global [%0], [%1], 16;" :: "r"(dst), "l"(src));
}
#define CP_COMMIT() asm volatile("cp.async.commit_group;" ::: "memory")
#define CP_WAIT0()  asm volatile("cp.async.wait_group 0;" ::: "memory")

__device__ __forceinline__ void ldsm4(uint32_t& r0, uint32_t& r1, uint32_t& r2, uint32_t& r3,
                                      uint32_t addr) {
    asm volatile("ldmatrix.sync.aligned.m8n8.x4.shared.b16 {%0,%1,%2,%3}, [%4];"
                 : "=r"(r0), "=r"(r1), "=r"(r2), "=r"(r3) : "r"(addr));
}
__device__ __forceinline__ void ldsm4t(uint32_t& r0, uint32_t& r1, uint32_t& r2, uint32_t& r3,
                                       uint32_t addr) {
    asm volatile("ldmatrix.sync.aligned.m8n8.x4.trans.shared.b16 {%0,%1,%2,%3}, [%4];"
                 : "=r"(r0), "=r"(r1), "=r"(r2), "=r"(r3) : "r"(addr));
}
__device__ __forceinline__ void mma_f16(float* d, const uint32_t a[4],
                                        uint32_t b0, uint32_t b1) {
    asm volatile(
        "mma.sync.aligned.m16n8k16.row.col.f32.f16.f16.f32 "
        "{%0,%1,%2,%3}, {%4,%5,%6,%7}, {%8,%9}, {%0,%1,%2,%3};"
        : "+f"(d[0]), "+f"(d[1]), "+f"(d[2]), "+f"(d[3])
        : "r"(a[0]), "r"(a[1]), "r"(a[2]), "r"(a[3]), "r"(b0), "r"(b1));
}
__device__ __forceinline__ uint32_t pack2h(float p0, float p1) {
    uint32_t r;
    asm("cvt.rn.f16x2.f32 %0, %1, %2;" : "=r"(r) : "f"(p1), "f"(p0));
    return r;
}

__device__ __forceinline__ void load_afrags(uint32_t f[4][4], uint32_t abase, int m0, int lane) {
    const uint32_t aaddr = abase + (uint32_t)(m0 + (lane & 15)) * ROWB
                         + (uint32_t)((lane >> 4) << 3) * 2;
#pragma unroll
    for (int kk = 0; kk < 4; kk++)
        ldsm4(f[kk][0], f[kk][1], f[kk][2], f[kk][3], aaddr + kk * 32);
}

// ---------------------------------------------------------------------------
// kernPre: tiled r-transpose (b<64) / V fp16 (b<320) / w2 fp16 (b<384)
// ---------------------------------------------------------------------------
__global__ __launch_bounds__(256) void kernPre(const float* __restrict__ r,
                                               const float* __restrict__ v,
                                               const float* __restrict__ w2) {
    const int b = blockIdx.x;
    const int t = threadIdx.x;
    if (b < 64) {
        // tiled transpose: r[n][t][rr] -> g_rT[n][rr][t], 128-token tile
        const int n = b >> 3, t0 = (b & 7) * 128;
        __shared__ float tile[RD][132];
        for (int i = t; i < 2048; i += 256) {          // 2048 float4 = 128t x 64rr
            int tt = i >> 4, rr4 = (i & 15) * 4;
            float4 rv = *(const float4*)&r[(size_t)(n * IJ + t0 + tt) * RD + rr4];
            tile[rr4 + 0][tt] = rv.x;
            tile[rr4 + 1][tt] = rv.y;
            tile[rr4 + 2][tt] = rv.z;
            tile[rr4 + 3][tt] = rv.w;
        }
        __syncthreads();
        for (int i = t; i < 2048; i += 256) {
            int rr = i >> 5, tq = (i & 31) * 4;
            float4 ov = *(const float4*)&tile[rr][tq];
            *(float4*)&g_rT[(size_t)(n * RD + rr) * IJ + t0 + tq] = ov;
        }
    } else if (b < 320) {
        for (int i = (b - 64) * 256 + t; i < NB * IJ * VD; i += 256 * 256)
            g_v16[i] = __half_as_ushort(__float2half_rn(v[i]));
    } else {
        const int rr = b - 320;
        const int h = t & 127;
        for (int x = t >> 7; x < XD; x += 2)
            g_w216[(rr * XD + x) * HD + h] =
                __half_as_ushort(__float2half_rn(w2[(x * RD + rr) * HD + h]));
    }
}

// ---------------------------------------------------------------------------
// kernA: A[n,rr,v,h] = sum_u w1*u -> fp16 g_a16[n][rr][v][h]; zeroes out.
// ---------------------------------------------------------------------------
__global__ __launch_bounds__(128) void kernA(const float* __restrict__ u,
                                             const float* __restrict__ w1,
                                             float* __restrict__ out) {
    const int rr = blockIdx.x;
    const int vv0 = blockIdx.y * 4;
    const int t = threadIdx.x;
    const int vloc = t >> 5;
    const int h4 = (t & 31) * 4;
    const int vv = vv0 + vloc;

    *(float4*)&out[(size_t)((blockIdx.y * RD + blockIdx.x) * 128 + t) * 4] =
        make_float4(0.f, 0.f, 0.f, 0.f);

    __shared__ float us[4][NB][UD];
    for (int idx = t; idx < NB * UD; idx += 128) {
        int n = idx >> 6, uu = idx & 63;
        float4 uv = *(const float4*)&u[((n * RD + rr) * UD + uu) * VD + vv0];
        us[0][n][uu] = uv.x;
        us[1][n][uu] = uv.y;
        us[2][n][uu] = uv.z;
        us[3][n][uu] = uv.w;
    }
    __syncthreads();

    float acc[NB][4];
#pragma unroll
    for (int n = 0; n < NB; n++)
#pragma unroll
        for (int j = 0; j < 4; j++) acc[n][j] = 0.f;

    const float* w1p = w1 + ((size_t)(rr * UD) * VD + vv) * HD + h4;
#pragma unroll 8
    for (int uu = 0; uu < UD; uu++) {
        float4 wv = *(const float4*)(w1p + (size_t)uu * (VD * HD));
#pragma unroll
        for (int n = 0; n < NB; n++) {
            float s = us[vloc][n][uu];
            acc[n][0] = fmaf(wv.x, s, acc[n][0]);
            acc[n][1] = fmaf(wv.y, s, acc[n][1]);
            acc[n][2] = fmaf(wv.z, s, acc[n][2]);
            acc[n][3] = fmaf(wv.w, s, acc[n][3]);
        }
    }
#pragma unroll
    for (int n = 0; n < NB; n++) {
        ushort4 h4v;
        h4v.x = __half_as_ushort(__float2half_rn(acc[n][0]));
        h4v.y = __half_as_ushort(__float2half_rn(acc[n][1]));
        h4v.z = __half_as_ushort(__float2half_rn(acc[n][2]));
        h4v.w = __half_as_ushort(__float2half_rn(acc[n][3]));
        *(ushort4*)&g_a16[((size_t)(n * RD + rr) * VD + vv) * HD + h4] = h4v;
    }
}

// ---------------------------------------------------------------------------
// kernB: 128 thr, quarter-tile 64m x 64c x 16rr, 1024 CTAs (fine-grain balance),
// pure fp16 mma + fp32 accumulate, single-barrier cp.async pipeline, 4 CTAs/SM.
// ---------------------------------------------------------------------------
extern __shared__ unsigned char smemB[];

__device__ __forceinline__ void issue_fills(uint32_t sbuf, int n, int rr, int h0g, int tid) {
    const unsigned short* a1 = g_a16 + ((size_t)(n * RD + rr) * VD) * HD + h0g;
#pragma unroll
    for (int j = 0; j < 4; j++) {
        int i = tid + j * 128;               // 0..511
        int row = i >> 3, c = i & 7;
        uint32_t dst = sbuf + row * ROWB + c * 16;
        cp16(dst,         a1 + (size_t)row * HD + c * 8);
        cp16(dst + TILEB, g_w216 + (size_t)(rr * XD + row) * HD + h0g + c * 8);
    }
}

__global__ __launch_bounds__(128, 4) void kernB(float* __restrict__ out) {
    const uint32_t sb = smem_u32(smemB);
    const int tid = threadIdx.x, lane = tid & 31, w = tid >> 5;
    const int tile = blockIdx.x, n = blockIdx.y, z = blockIdx.z;
    const int token0 = tile * TM;
    const int h0g = (z & 1) * HC;
    const int rr0 = (z >> 1) * RRG;
    const int m0 = w * 16;
    const int mrow = lane >> 2;
    const int stag = (blockIdx.x & 3) * 4;   // phase stagger through the 16-rr ring

    issue_fills(sb + SOFF_BUF, n, rr0 + (stag & (RRG - 1)), h0g, tid);
    CP_COMMIT();

    // V tile fill (once): 64 rows x 128B, 144B stride
    {
        const uint4* s1 = (const uint4*)(g_v16 + (size_t)(n * IJ + token0) * VD);
#pragma unroll
        for (int j = 0; j < 4; j++) {
            int i = tid + j * 128;           // 0..511
            int row = i >> 3, c = i & 7;
            *(uint4*)(smemB + SOFF_V + row * ROWB + c * 16) = s1[i];
        }
    }
    __syncthreads();

    uint32_t vf[4][4];
    load_afrags(vf, sb + SOFF_V, m0, lane);

    const uint32_t toff = (uint32_t)(((lane >> 3) & 1) * 8 + (lane & 7)) * ROWB
                        + (uint32_t)((lane >> 4) << 3) * 2;
    const uint32_t woff = (uint32_t)(((lane >> 4) << 3) + (lane & 7)) * ROWB
                        + (uint32_t)(((lane >> 3) & 1) << 3) * 2;

    float oc[8][4];
#pragma unroll
    for (int t2 = 0; t2 < 8; t2++)
#pragma unroll
        for (int j = 0; j < 4; j++) oc[t2][j] = 0.f;

    for (int rl = 0; rl < RRG; rl++) {
        const int rr = rr0 + ((rl + stag) & (RRG - 1));
        const uint32_t sbuf = sb + SOFF_BUF + (rl & 1) * BUFB;

        const float rsc0 = g_rT[(n * RD + rr) * IJ + token0 + m0 + mrow];
        const float rsc8 = g_rT[(n * RD + rr) * IJ + token0 + m0 + mrow + 8];

        CP_WAIT0();
        __syncthreads();
        if (rl + 1 < RRG) {
            issue_fills(sb + SOFF_BUF + ((rl & 1) ^ 1) * BUFB,
                        n, rr0 + ((rl + 1 + stag) & (RRG - 1)), h0g, tid);
            CP_COMMIT();
        }

        // ---- pipelined per h-chunk (16 cols): stage1 -> cvt -> stage2 ----
#pragma unroll
        for (int c2 = 0; c2 < 4; c2++) {
            float p0[4] = {0.f, 0.f, 0.f, 0.f};
            float p1[4] = {0.f, 0.f, 0.f, 0.f};
#pragma unroll
            for (int kk = 0; kk < 4; kk++) {
                uint32_t b0, b1, b2, b3;
                ldsm4t(b0, b1, b2, b3, sbuf + toff + kk * 16 * ROWB + c2 * 32);
                mma_f16(p0, vf[kk], b0, b1);
                mma_f16(p1, vf[kk], b2, b3);
            }

            uint32_t fp[4];
            fp[0] = pack2h(fmaxf(p0[0], 0.f) * rsc0, fmaxf(p0[1], 0.f) * rsc0);
            fp[1] = pack2h(fmaxf(p0[2], 0.f) * rsc8, fmaxf(p0[3], 0.f) * rsc8);
            fp[2] = pack2h(fmaxf(p1[0], 0.f) * rsc0, fmaxf(p1[1], 0.f) * rsc0);
            fp[3] = pack2h(fmaxf(p1[2], 0.f) * rsc8, fmaxf(p1[3], 0.f) * rsc8);

#pragma unroll
            for (int nt = 0; nt < 4; nt++) {
                uint32_t b0, b1, b2, b3;
                ldsm4(b0, b1, b2, b3, sbuf + TILEB + woff + nt * 16 * ROWB + c2 * 32);
                mma_f16(oc[2 * nt],     fp, b0, b1);
                mma_f16(oc[2 * nt + 1], fp, b2, b3);
            }
        }
    }

    // final epilogue: 8 partial CTAs per out element (2 hblk x 4 rr-groups)
    {
        float* op = out + (size_t)(n * IJ + token0 + m0 + mrow) * XD;
#pragma unroll
        for (int nt = 0; nt < 8; nt++) {
            const int x = nt * 8 + 2 * (lane & 3);
            atomicAdd(op + x,     oc[nt][0]);
            atomicAdd(op + x + 1, oc[nt][1]);
            atomicAdd(op + 8 * XD + x,     oc[nt][2]);
            atomicAdd(op + 8 * XD + x + 1, oc[nt][3]);
        }
    }
}

// ---------------------------------------------------------------------------
extern "C" void kernel_launch(void* const* d_in, const int* in_sizes, int n_in,
                              void* d_out, int out_size) {
    const float* r  = (const float*)d_in[0];
    const float* u  = (const float*)d_in[1];
    const float* v  = (const float*)d_in[2];
    const float* w1 = (const float*)d_in[3];
    const float* w2 = (const float*)d_in[4];
    float* out = (float*)d_out;
    (void)in_sizes; (void)n_in; (void)out_size;

    static int attr_done = 0;
    if (!attr_done) {
        cudaFuncSetAttribute(kernB, cudaFuncAttributeMaxDynamicSharedMemorySize, SMEM_TOTAL);
        attr_done = 1;
    }

    kernPre<<<384, 256>>>(r, v, w2);
    kernA<<<dim3(RD, 16), 128>>>(u, w1, out);
    kernB<<<dim3(IJ / TM, NB, 8), 128, SMEM_TOTAL>>>(out);
}